// round 2
// baseline (speedup 1.0000x reference)
#include <cuda_runtime.h>

#define NB   2048   // batch == ne == 2048
#define ND   128    // dims
#define TILE 64     // output tile edge
#define KCH  64     // dims per smem stage

// Scratch (allocation-free rule: __device__ globals)
__device__ float g_XT[ND * NB];   // transposed, attn-scaled inputs   [d][b]
__device__ float g_ET[ND * NB];   // transposed, attn-scaled exemplars[d][e]
__device__ float g_P[NB];         // -C * rowsum(attn*x) per batch row
__device__ float g_Q[NB];         // -C * rowsum(attn*e) per exemplar

// ---------------------------------------------------------------------------
// Prep: scale by attn, write transposed, compute -C * rowsum.
// grid = 2048 blocks (one row), 128 threads (one per dim).
// ---------------------------------------------------------------------------
__global__ void prep_kernel(const float* __restrict__ src,
                            const float* __restrict__ attn,
                            float* __restrict__ dstT,
                            float* __restrict__ negCsum)
{
    int row = blockIdx.x;
    int d   = threadIdx.x;
    float v = attn[d] * src[row * ND + d];
    dstT[d * NB + row] = v;

    // block reduce (128 threads = 4 warps)
    float s = v;
    #pragma unroll
    for (int o = 16; o > 0; o >>= 1)
        s += __shfl_down_sync(0xffffffffu, s, o);
    __shared__ float ws[4];
    if ((d & 31) == 0) ws[d >> 5] = s;
    __syncthreads();
    if (d == 0)
        negCsum[row] = -6.5f * (ws[0] + ws[1] + ws[2] + ws[3]);
}

// ---------------------------------------------------------------------------
// Main: 64x64 output tile per block, 256 threads, 4x4 register micro-tile.
// acc[b,e] = sum_d min(X'[d,b], E'[d,e]);  out = expf(P[b] + Q[e] + 2C*acc)
// ---------------------------------------------------------------------------
__global__ __launch_bounds__(256) void alcove_main(float* __restrict__ out)
{
    __shared__ float Xs[KCH * TILE];   // [d-chunk][64 batch rows]  32KB total
    __shared__ float Es[KCH * TILE];

    int tid = threadIdx.x;
    int tx  = tid & 15;        // exemplar-direction thread coord
    int ty  = tid >> 4;        // batch-direction thread coord
    int rb  = blockIdx.y * TILE;   // batch tile base
    int cb  = blockIdx.x * TILE;   // exemplar tile base

    float acc[4][4];
    #pragma unroll
    for (int i = 0; i < 4; i++)
        #pragma unroll
        for (int j = 0; j < 4; j++)
            acc[i][j] = 0.0f;

    const float4* gx = (const float4*)g_XT;
    const float4* ge = (const float4*)g_ET;
    float4* xs4 = (float4*)Xs;
    float4* es4 = (float4*)Es;

    #pragma unroll 1
    for (int kb = 0; kb < ND / KCH; kb++) {
        // Load stage: 64 d-rows x 64 floats each = 1024 float4 per matrix.
        // tid -> (d = fi>>4, q = fi&15): LDG 256B-contiguous, STS conflict-free.
        #pragma unroll
        for (int k = 0; k < 4; k++) {
            int fi = tid + k * 256;
            int d  = fi >> 4;
            int q  = fi & 15;
            int gofs = (kb * KCH + d) * (NB / 4);
            xs4[d * (TILE / 4) + q] = gx[gofs + (rb >> 2) + q];
            es4[d * (TILE / 4) + q] = ge[gofs + (cb >> 2) + q];
        }
        __syncthreads();

        #pragma unroll 8
        for (int d = 0; d < KCH; d++) {
            float4 xv = *(const float4*)&Xs[d * TILE + ty * 4];
            float4 ev = *(const float4*)&Es[d * TILE + tx * 4];
            float x[4] = {xv.x, xv.y, xv.z, xv.w};
            float e[4] = {ev.x, ev.y, ev.z, ev.w};
            #pragma unroll
            for (int i = 0; i < 4; i++)
                #pragma unroll
                for (int j = 0; j < 4; j++)
                    acc[i][j] += fminf(x[i], e[j]);   // FMNMX(alu) + FADD(fma)
        }
        __syncthreads();
    }

    // Epilogue: out = exp(P + Q + 2C*acc), 2C = 13.
    float q0 = g_Q[cb + tx * 4 + 0];
    float q1 = g_Q[cb + tx * 4 + 1];
    float q2 = g_Q[cb + tx * 4 + 2];
    float q3 = g_Q[cb + tx * 4 + 3];
    #pragma unroll
    for (int i = 0; i < 4; i++) {
        int r = rb + ty * 4 + i;
        float p = g_P[r];
        float4 o;
        o.x = __expf(fmaf(13.0f, acc[i][0], p + q0));
        o.y = __expf(fmaf(13.0f, acc[i][1], p + q1));
        o.z = __expf(fmaf(13.0f, acc[i][2], p + q2));
        o.w = __expf(fmaf(13.0f, acc[i][3], p + q3));
        *(float4*)&out[r * NB + cb + tx * 4] = o;
    }
}

// ---------------------------------------------------------------------------
extern "C" void kernel_launch(void* const* d_in, const int* in_sizes, int n_in,
                              void* d_out, int out_size)
{
    const float* inputs    = (const float*)d_in[0];
    const float* exemplars = (const float*)d_in[1];
    const float* attn      = (const float*)d_in[2];
    float* out = (float*)d_out;

    float *xt, *et, *p, *q;
    cudaGetSymbolAddress((void**)&xt, g_XT);
    cudaGetSymbolAddress((void**)&et, g_ET);
    cudaGetSymbolAddress((void**)&p,  g_P);
    cudaGetSymbolAddress((void**)&q,  g_Q);

    prep_kernel<<<NB, ND>>>(inputs,    attn, xt, p);
    prep_kernel<<<NB, ND>>>(exemplars, attn, et, q);

    dim3 grid(NB / TILE, NB / TILE);   // 32 x 32 = 1024 tiles
    alcove_main<<<grid, 256>>>(out);
}

// round 4
// speedup vs baseline: 1.0849x; 1.0849x over previous
#include <cuda_runtime.h>

#define NB   2048   // batch == ne == 2048
#define ND   128    // dims
#define TILE 64     // output tile edge
#define KCH  64     // dims per smem stage

// Scratch (allocation-free rule: __device__ globals)
__device__ float g_XT[ND * NB];   // transposed, attn-scaled inputs   [d][b]
__device__ float g_ET[ND * NB];   // transposed, attn-scaled exemplars[d][e]
__device__ float g_P[NB];         // -C * rowsum(attn*x) per batch row
__device__ float g_Q[NB];         // -C * rowsum(attn*e) per exemplar

// ---------------------------------------------------------------------------
// Prep: ONE launch for both matrices. Each block transposes 32 rows x 128
// dims through padded smem: coalesced 128B loads AND coalesced 128B stores,
// attn-scaling + (-C)*rowsum fused in.
// grid = 128 blocks (64 per matrix), 256 threads.
// ---------------------------------------------------------------------------
__global__ __launch_bounds__(256) void prep2_kernel(
    const float* __restrict__ X, const float* __restrict__ E,
    const float* __restrict__ attn)
{
    __shared__ float a[ND];
    __shared__ float T[32][ND + 1];      // stride 129: conflict-free col reads

    int bid = blockIdx.x;
    bool isE = bid >= 64;
    const float* src = isE ? E : X;
    float* dstT      = isE ? g_ET : g_XT;
    float* sums      = isE ? g_Q  : g_P;
    int rowbase = (bid & 63) * 32;

    int t = threadIdx.x;
    if (t < ND) a[t] = attn[t];
    __syncthreads();

    // Load 32 rows x 128 dims, scale by attn, partial row-sum.
    // thread t -> row r = t>>3, dim segment seg = t&7 (16 dims each).
    int r   = t >> 3;
    int seg = t & 7;
    const float4* srow = (const float4*)&src[(rowbase + r) * ND + seg * 16];
    float s = 0.0f;
    #pragma unroll
    for (int k = 0; k < 4; k++) {
        float4 v = srow[k];
        int d = seg * 16 + k * 4;
        v.x *= a[d + 0]; v.y *= a[d + 1]; v.z *= a[d + 2]; v.w *= a[d + 3];
        T[r][d + 0] = v.x; T[r][d + 1] = v.y;
        T[r][d + 2] = v.z; T[r][d + 3] = v.w;
        s += v.x + v.y + v.z + v.w;
    }
    // reduce the 8 segment-partials of each row (consecutive lanes)
    s += __shfl_down_sync(0xffffffffu, s, 4);
    s += __shfl_down_sync(0xffffffffu, s, 2);
    s += __shfl_down_sync(0xffffffffu, s, 1);
    if (seg == 0) sums[rowbase + r] = -6.5f * s;
    __syncthreads();

    // Transposed write: 128 d-rows x 32 rows = 1024 float4, coalesced STG.128.
    #pragma unroll
    for (int k = 0; k < 4; k++) {
        int o  = t + k * 256;        // output float4 index 0..1023
        int d  = o >> 3;             // 0..127
        int rg = o & 7;              // group of 4 consecutive rows
        float4 v;
        v.x = T[rg * 4 + 0][d];
        v.y = T[rg * 4 + 1][d];
        v.z = T[rg * 4 + 2][d];
        v.w = T[rg * 4 + 3][d];
        *(float4*)&dstT[d * NB + rowbase + rg * 4] = v;
    }
}

// ---------------------------------------------------------------------------
// Main: 64x64 output tile per block, 256 threads, 4x4 register micro-tile.
// acc[b,e] = sum_d min(X'[d,b], E'[d,e]);  out = expf(P[b] + Q[e] + 2C*acc)
// ---------------------------------------------------------------------------
__global__ __launch_bounds__(256) void alcove_main(float* __restrict__ out)
{
    __shared__ float Xs[KCH * TILE];   // 32KB total
    __shared__ float Es[KCH * TILE];

    int tid = threadIdx.x;
    int tx  = tid & 15;
    int ty  = tid >> 4;
    int rb  = blockIdx.y * TILE;
    int cb  = blockIdx.x * TILE;

    float acc[4][4];
    #pragma unroll
    for (int i = 0; i < 4; i++)
        #pragma unroll
        for (int j = 0; j < 4; j++)
            acc[i][j] = 0.0f;

    const float4* gx = (const float4*)g_XT;
    const float4* ge = (const float4*)g_ET;
    float4* xs4 = (float4*)Xs;
    float4* es4 = (float4*)Es;

    #pragma unroll 1
    for (int kb = 0; kb < ND / KCH; kb++) {
        #pragma unroll
        for (int k = 0; k < 4; k++) {
            int fi = tid + k * 256;
            int d  = fi >> 4;
            int q  = fi & 15;
            int gofs = (kb * KCH + d) * (NB / 4);
            xs4[d * (TILE / 4) + q] = gx[gofs + (rb >> 2) + q];
            es4[d * (TILE / 4) + q] = ge[gofs + (cb >> 2) + q];
        }
        __syncthreads();

        #pragma unroll 8
        for (int d = 0; d < KCH; d++) {
            float4 xv = *(const float4*)&Xs[d * TILE + ty * 4];
            float4 ev = *(const float4*)&Es[d * TILE + tx * 4];
            float x[4] = {xv.x, xv.y, xv.z, xv.w};
            float e[4] = {ev.x, ev.y, ev.z, ev.w};
            #pragma unroll
            for (int i = 0; i < 4; i++)
                #pragma unroll
                for (int j = 0; j < 4; j++)
                    acc[i][j] += fminf(x[i], e[j]);   // FMNMX(alu) + FADD(fma)
        }
        __syncthreads();
    }

    float q0 = g_Q[cb + tx * 4 + 0];
    float q1 = g_Q[cb + tx * 4 + 1];
    float q2 = g_Q[cb + tx * 4 + 2];
    float q3 = g_Q[cb + tx * 4 + 3];
    #pragma unroll
    for (int i = 0; i < 4; i++) {
        int r = rb + ty * 4 + i;
        float p = g_P[r];
        float4 o;
        o.x = __expf(fmaf(13.0f, acc[i][0], p + q0));
        o.y = __expf(fmaf(13.0f, acc[i][1], p + q1));
        o.z = __expf(fmaf(13.0f, acc[i][2], p + q2));
        o.w = __expf(fmaf(13.0f, acc[i][3], p + q3));
        *(float4*)&out[r * NB + cb + tx * 4] = o;
    }
}

// ---------------------------------------------------------------------------
extern "C" void kernel_launch(void* const* d_in, const int* in_sizes, int n_in,
                              void* d_out, int out_size)
{
    const float* inputs    = (const float*)d_in[0];
    const float* exemplars = (const float*)d_in[1];
    const float* attn      = (const float*)d_in[2];
    float* out = (float*)d_out;

    prep2_kernel<<<128, 256>>>(inputs, exemplars, attn);

    dim3 grid(NB / TILE, NB / TILE);   // 32 x 32 = 1024 tiles
    alcove_main<<<grid, 256>>>(out);
}